// round 1
// baseline (speedup 1.0000x reference)
#include <cuda_runtime.h>

// BSpline_76158360093294
// out[b,o] = sum_{i,c} basis(x[b,i])[c] * cp[i,c,o]
// x: (65536,64) f32, cp: (64,12,64) f32, out: (65536,64) f32
// Cubic clamped B-spline, 16 knots, 12 basis fns, only 4 non-zero per x.

#define ROWS_PER_CTA 8
#define CTA_THREADS 128
#define DIMS 64
#define NBASIS 12

__global__ __launch_bounds__(CTA_THREADS)
void bspline_fused_kernel(const float* __restrict__ x,
                          const float* __restrict__ cp,
                          float* __restrict__ out,
                          int nrows)
{
    __shared__ float  T[16];                       // knot vector
    __shared__ float4 bas[ROWS_PER_CTA][DIMS];     // 4 nonzero basis values
    __shared__ int    offs[ROWS_PER_CTA][DIMS];    // (i*12 + c0) * 64

    const int t = threadIdx.x;

    // Knots: clamped uniform, T[k] = clamp(k-3, 0, 9) / 9 (correctly-rounded f32
    // division matches numpy's float32 knot construction).
    if (t < 16) {
        int k = t - 3;
        k = max(0, min(9, k));
        T[t] = (float)k / 9.0f;
    }
    __syncthreads();

    const int row0 = blockIdx.x * ROWS_PER_CTA;

    // ---------------- Phase 1: basis evaluation ----------------
    // 8 rows * 64 dims = 512 (row,i) pairs over 128 threads -> 4 each.
    #pragma unroll
    for (int s = 0; s < (ROWS_PER_CTA * DIMS) / CTA_THREADS; s++) {
        const int p = t + s * CTA_THREADS;
        const int r = p >> 6;
        const int i = p & 63;
        const int row = row0 + r;
        if (row < nrows) {
            float xc = x[row * DIMS + i];
            xc = fminf(fmaxf(xc, 0.0f), 1.0f);

            // Span index j in [3,11]: largest j with xc >= T[j] (capped).
            // (At xc==1, j=11 and de Boor yields (0,0,0,1) == reference.)
            int j = 3;
            #pragma unroll
            for (int k = 4; k <= 11; k++) j += (xc >= T[k]) ? 1 : 0;

            // de Boor: 4 nonzero cubic basis values N0..N3 at span j.
            const float l1 = xc - T[j];
            const float r1 = T[j + 1] - xc;
            const float l2 = xc - T[j - 1];
            const float r2 = T[j + 2] - xc;
            const float l3 = xc - T[j - 2];
            const float r3 = T[j + 3] - xc;

            float N0 = 1.0f, N1, N2, N3, tmp, sv;
            // d = 1
            tmp = __fdividef(N0, r1 + l1);
            N0 = r1 * tmp;
            N1 = l1 * tmp;
            // d = 2
            tmp = __fdividef(N0, r1 + l2);
            N0 = r1 * tmp;
            sv = l2 * tmp;
            tmp = __fdividef(N1, r2 + l1);
            N1 = sv + r2 * tmp;
            N2 = l1 * tmp;
            // d = 3
            tmp = __fdividef(N0, r1 + l3);
            N0 = r1 * tmp;
            sv = l3 * tmp;
            tmp = __fdividef(N1, r2 + l2);
            N1 = sv + r2 * tmp;
            sv = l2 * tmp;
            tmp = __fdividef(N2, r3 + l1);
            N2 = sv + r3 * tmp;
            N3 = l1 * tmp;

            bas[r][i]  = make_float4(N0, N1, N2, N3);
            offs[r][i] = (i * NBASIS + (j - 3)) * 64;   // first cp element index (o=0)
        }
    }
    __syncthreads();

    // ---------------- Phase 2: sparse contraction ----------------
    // thread -> (row rr in 0..7, output quad oq in 0..15), 4 outputs per thread.
    const int oq = t & 15;
    const int rr = t >> 4;
    const int row = row0 + rr;
    if (row >= nrows) return;

    const float4* __restrict__ cp4 = (const float4*)cp;
    float4 acc = make_float4(0.f, 0.f, 0.f, 0.f);

    #pragma unroll 4
    for (int i = 0; i < DIMS; i++) {
        const float4 w = bas[rr][i];
        const int b4 = (offs[rr][i] >> 2) + oq;   // float4 index, 16B aligned
        const float4 v0 = cp4[b4];                // c0
        const float4 v1 = cp4[b4 + 16];           // c0+1  (stride 64 floats)
        const float4 v2 = cp4[b4 + 32];           // c0+2
        const float4 v3 = cp4[b4 + 48];           // c0+3

        acc.x = fmaf(w.x, v0.x, acc.x);
        acc.y = fmaf(w.x, v0.y, acc.y);
        acc.z = fmaf(w.x, v0.z, acc.z);
        acc.w = fmaf(w.x, v0.w, acc.w);

        acc.x = fmaf(w.y, v1.x, acc.x);
        acc.y = fmaf(w.y, v1.y, acc.y);
        acc.z = fmaf(w.y, v1.z, acc.z);
        acc.w = fmaf(w.y, v1.w, acc.w);

        acc.x = fmaf(w.z, v2.x, acc.x);
        acc.y = fmaf(w.z, v2.y, acc.y);
        acc.z = fmaf(w.z, v2.z, acc.z);
        acc.w = fmaf(w.z, v2.w, acc.w);

        acc.x = fmaf(w.w, v3.x, acc.x);
        acc.y = fmaf(w.w, v3.y, acc.y);
        acc.z = fmaf(w.w, v3.z, acc.z);
        acc.w = fmaf(w.w, v3.w, acc.w);
    }

    ((float4*)out)[row * (DIMS / 4) + oq] = acc;
}

extern "C" void kernel_launch(void* const* d_in, const int* in_sizes, int n_in,
                              void* d_out, int out_size)
{
    const float* x  = (const float*)d_in[0];   // (65536, 64)
    const float* cp = (const float*)d_in[1];   // (64, 12, 64)
    float* out = (float*)d_out;

    const int nrows = in_sizes[0] / DIMS;
    const int grid = (nrows + ROWS_PER_CTA - 1) / ROWS_PER_CTA;

    bspline_fused_kernel<<<grid, CTA_THREADS>>>(x, cp, out, nrows);
}

// round 3
// speedup vs baseline: 2.7437x; 2.7437x over previous
#include <cuda_runtime.h>
#include <cuda_fp16.h>
#include <cstdint>

// ============================================================================
// BSpline via warp-level mma.sync (HMMA, compute_103-legal).
//   out[b,o] = sum_{i,c} basis(x[b,i])[c] * cp[i,c,o]
//   = GEMM: A (rows x 768) * B (768 x 64), k = i*12 + c (cp is already B[k][o]).
//   A: 4 nonzeros per 12-wide window, built densely in SMEM fp16 per 128-row
//   tile. B: prepacked in mma fragment order, fetched via coalesced LDG.64.
// ============================================================================

#define DIMS 64
#define KDIM 768
#define KSTEPS 48          // 768 / 16
#define M_TILE 128
#define THREADS 256

#define A_PITCH_B 1552     // bytes per A row: 776 halfs; odd multiple of 16B
#define SMEM_A_BYTES (M_TILE * A_PITCH_B)        // 198656
#define SMEM_TK SMEM_A_BYTES                     // 16 floats
#define SMEM_TOTAL (SMEM_A_BYTES + 64)

// B fragments: [kstep][n][kq] -> uint2 {h(k0),h(k0+1) | h(k0+8),h(k0+9)}
// k0 = kstep*16 + kq*2, value = cp[k][n].
__device__ uint2 g_Bf[KSTEPS * 64 * 4];

static __device__ __forceinline__ uint32_t s2u(const void* p) {
    uint32_t a;
    asm("{ .reg .u64 t; cvta.to.shared.u64 t, %1; cvt.u32.u64 %0, t; }" : "=r"(a) : "l"(p));
    return a;
}

static __device__ __forceinline__ void ldsm_x4(uint32_t& r0, uint32_t& r1,
                                               uint32_t& r2, uint32_t& r3,
                                               uint32_t addr) {
    asm volatile("ldmatrix.sync.aligned.m8n8.x4.shared.b16 {%0,%1,%2,%3}, [%4];"
                 : "=r"(r0), "=r"(r1), "=r"(r2), "=r"(r3) : "r"(addr));
}

static __device__ __forceinline__ void mma16816(float& d0, float& d1, float& d2, float& d3,
                                                uint32_t a0, uint32_t a1, uint32_t a2, uint32_t a3,
                                                uint32_t b0, uint32_t b1) {
    asm volatile(
        "mma.sync.aligned.m16n8k16.row.col.f32.f16.f16.f32 "
        "{%0,%1,%2,%3}, {%4,%5,%6,%7}, {%8,%9}, {%0,%1,%2,%3};"
        : "+f"(d0), "+f"(d1), "+f"(d2), "+f"(d3)
        : "r"(a0), "r"(a1), "r"(a2), "r"(a3), "r"(b0), "r"(b1));
}

// ---------------------------------------------------------------------------
// Prep: cp fp32 (seen as [k][o], k = i*12+c) -> fragment-ordered fp16 g_Bf.
// ---------------------------------------------------------------------------
__global__ void bspline_prep_kernel(const float* __restrict__ cp) {
    int tid = blockIdx.x * blockDim.x + threadIdx.x;
    if (tid < KSTEPS * 64 * 4) {
        int kq = tid & 3;
        int n = (tid >> 2) & 63;
        int kstep = tid >> 8;
        int k0 = kstep * 16 + kq * 2;
        __half h0 = __float2half_rn(cp[(k0 + 0) * 64 + n]);
        __half h1 = __float2half_rn(cp[(k0 + 1) * 64 + n]);
        __half h2 = __float2half_rn(cp[(k0 + 8) * 64 + n]);
        __half h3 = __float2half_rn(cp[(k0 + 9) * 64 + n]);
        uint2 v;
        v.x = (uint32_t)__half_as_ushort(h0) | ((uint32_t)__half_as_ushort(h1) << 16);
        v.y = (uint32_t)__half_as_ushort(h2) | ((uint32_t)__half_as_ushort(h3) << 16);
        g_Bf[tid] = v;
    }
}

// ---------------------------------------------------------------------------
// Main kernel: one CTA = 128 rows, 8 warps = 4(M) x 2(N), warp tile M32xN32.
// ---------------------------------------------------------------------------
__global__ __launch_bounds__(THREADS, 1)
void bspline_hmma_kernel(const float* __restrict__ x,
                         float* __restrict__ out,
                         int nrows)
{
    extern __shared__ char sm[];
    const uint32_t sb = s2u(sm);
    const int t = threadIdx.x;
    const int wid = t >> 5;
    const int lid = t & 31;
    const int row0 = blockIdx.x * M_TILE;

    float* Tk = (float*)(sm + SMEM_TK);
    if (t < 16) {
        int k = t - 3;
        k = max(0, min(9, k));
        Tk[t] = (float)k / 9.0f;
    }
    __syncthreads();

    // ---------------- Phase 1: build A tile in SMEM (fp16) ----------------
    // 128 rows x 64 i-windows = 8192 pairs, 32 per thread, i fastest (coalesced x).
    #pragma unroll
    for (int s = 0; s < 32; s++) {
        const int p = s * THREADS + t;
        const int r = p >> 6;
        const int i = p & 63;
        const int row = min(row0 + r, nrows - 1);

        float xc = __ldg(x + (size_t)row * DIMS + i);
        xc = fminf(fmaxf(xc, 0.0f), 1.0f);

        int j = 3;
        #pragma unroll
        for (int k = 4; k <= 11; k++) j += (xc >= Tk[k]) ? 1 : 0;

        const float l1 = xc - Tk[j];
        const float r1 = Tk[j + 1] - xc;
        const float l2 = xc - Tk[j - 1];
        const float r2 = Tk[j + 2] - xc;
        const float l3 = xc - Tk[j - 2];
        const float r3 = Tk[j + 3] - xc;

        float N0 = 1.0f, N1, N2, N3, tmp, sv;
        tmp = __fdividef(N0, r1 + l1); N0 = r1 * tmp; N1 = l1 * tmp;
        tmp = __fdividef(N0, r1 + l2); N0 = r1 * tmp; sv = l2 * tmp;
        tmp = __fdividef(N1, r2 + l1); N1 = sv + r2 * tmp; N2 = l1 * tmp;
        tmp = __fdividef(N0, r1 + l3); N0 = r1 * tmp; sv = l3 * tmp;
        tmp = __fdividef(N1, r2 + l2); N1 = sv + r2 * tmp; sv = l2 * tmp;
        tmp = __fdividef(N2, r3 + l1); N2 = sv + r3 * tmp; N3 = l1 * tmp;

        const int c0 = j - 3;   // 0..8
        unsigned short h0 = __half_as_ushort(__float2half_rn(N0));
        unsigned short h1 = __half_as_ushort(__float2half_rn(N1));
        unsigned short h2 = __half_as_ushort(__float2half_rn(N2));
        unsigned short h3 = __half_as_ushort(__float2half_rn(N3));

        // 12-half window at bytes [r*1552 + i*24, +24): zero then scatter.
        const uint32_t w = sb + (uint32_t)r * A_PITCH_B + (uint32_t)i * 24u;
        asm volatile("st.shared.u64 [%0], %1;" :: "r"(w),      "l"(0ULL) : "memory");
        asm volatile("st.shared.u64 [%0], %1;" :: "r"(w + 8),  "l"(0ULL) : "memory");
        asm volatile("st.shared.u64 [%0], %1;" :: "r"(w + 16), "l"(0ULL) : "memory");
        const uint32_t d = w + (uint32_t)c0 * 2u;
        asm volatile("st.shared.u16 [%0], %1;" :: "r"(d),     "h"(h0) : "memory");
        asm volatile("st.shared.u16 [%0], %1;" :: "r"(d + 2), "h"(h1) : "memory");
        asm volatile("st.shared.u16 [%0], %1;" :: "r"(d + 4), "h"(h2) : "memory");
        asm volatile("st.shared.u16 [%0], %1;" :: "r"(d + 6), "h"(h3) : "memory");
    }
    __syncthreads();

    // ---------------- Phase 2: mma.sync mainloop ----------------
    const int mbase = (wid >> 1) * 32;      // 0,32,64,96
    const int nbase = (wid & 1) * 32;       // 0,32

    // ldmatrix per-lane base addresses (two m16 tiles), k advances by 32B/step.
    const int lrow = (lid & 7) + ((lid >> 3) & 1) * 8;   // 0..15
    const int lcol = (lid >> 4) * 16;                     // 0 or 16 bytes
    uint32_t aAddr0 = sb + (uint32_t)(mbase + lrow)      * A_PITCH_B + lcol;
    uint32_t aAddr1 = sb + (uint32_t)(mbase + 16 + lrow) * A_PITCH_B + lcol;

    // B fragment per-lane base index: [kstep*256 + n*4 + kq]
    const uint2* __restrict__ Bf = g_Bf;
    const int bLane = (nbase + (lid >> 2)) * 4 + (lid & 3);

    float acc[2][4][4];
    #pragma unroll
    for (int mt = 0; mt < 2; mt++)
        #pragma unroll
        for (int nt = 0; nt < 4; nt++)
            #pragma unroll
            for (int q = 0; q < 4; q++) acc[mt][nt][q] = 0.0f;

    #pragma unroll 2
    for (int ks = 0; ks < KSTEPS; ks++) {
        uint32_t a0[4], a1[4];
        ldsm_x4(a0[0], a0[1], a0[2], a0[3], aAddr0 + ks * 32);
        ldsm_x4(a1[0], a1[1], a1[2], a1[3], aAddr1 + ks * 32);

        uint2 b[4];
        const int bi = ks * 256 + bLane;
        #pragma unroll
        for (int nt = 0; nt < 4; nt++) b[nt] = __ldg(Bf + bi + nt * 32);

        #pragma unroll
        for (int nt = 0; nt < 4; nt++) {
            mma16816(acc[0][nt][0], acc[0][nt][1], acc[0][nt][2], acc[0][nt][3],
                     a0[0], a0[1], a0[2], a0[3], b[nt].x, b[nt].y);
            mma16816(acc[1][nt][0], acc[1][nt][1], acc[1][nt][2], acc[1][nt][3],
                     a1[0], a1[1], a1[2], a1[3], b[nt].x, b[nt].y);
        }
    }

    // ---------------- Epilogue: direct float2 stores ----------------
    const int rquad = lid >> 2;              // 0..7
    const int npair = (lid & 3) * 2;         // 0,2,4,6
    #pragma unroll
    for (int mt = 0; mt < 2; mt++) {
        #pragma unroll
        for (int nt = 0; nt < 4; nt++) {
            const int col = nbase + nt * 8 + npair;
            const int rA = row0 + mbase + mt * 16 + rquad;
            const int rB = rA + 8;
            if (rA < nrows) {
                float2 v0 = make_float2(acc[mt][nt][0], acc[mt][nt][1]);
                *(float2*)(out + (size_t)rA * DIMS + col) = v0;
            }
            if (rB < nrows) {
                float2 v1 = make_float2(acc[mt][nt][2], acc[mt][nt][3]);
                *(float2*)(out + (size_t)rB * DIMS + col) = v1;
            }
        }
    }
}

extern "C" void kernel_launch(void* const* d_in, const int* in_sizes, int n_in,
                              void* d_out, int out_size)
{
    const float* x  = (const float*)d_in[0];   // (65536, 64)
    const float* cp = (const float*)d_in[1];   // (64, 12, 64) == B[768][64]
    float* out = (float*)d_out;

    const int nrows = in_sizes[0] / DIMS;

    bspline_prep_kernel<<<(KSTEPS * 64 * 4 + 255) / 256, 256>>>(cp);

    cudaFuncSetAttribute(bspline_hmma_kernel,
                         cudaFuncAttributeMaxDynamicSharedMemorySize, SMEM_TOTAL);
    const int grid = (nrows + M_TILE - 1) / M_TILE;
    bspline_hmma_kernel<<<grid, THREADS, SMEM_TOTAL>>>(x, out, nrows);
}

// round 4
// speedup vs baseline: 2.9437x; 1.0729x over previous
#include <cuda_runtime.h>
#include <cuda_fp16.h>
#include <cstdint>

// ============================================================================
// BSpline via warp-level mma.sync (HMMA).
//   out[b,o] = sum_{i,c} basis(x[b,i])[c] * cp[i,c,o]
//   = GEMM: A (rows x 768) * B (768 x 64), k = i*12 + c (cp is already B[k][o]).
// R4: M_TILE 128 -> 64 so SMEM ~97KB -> 2 CTAs/SM (occupancy fix).
//   Warp grid 4(M) x 2(N), warp tile M16 x N32.
// ============================================================================

#define DIMS 64
#define KDIM 768
#define KSTEPS 48          // 768 / 16
#define M_TILE 64
#define THREADS 256

#define A_PITCH_B 1552     // bytes per A row: 776 halfs; odd multiple of 16B
#define SMEM_A_BYTES (M_TILE * A_PITCH_B)        // 99328
#define SMEM_TK SMEM_A_BYTES                     // 16 floats
#define SMEM_TOTAL (SMEM_A_BYTES + 64)

// B fragments: [kstep][n][kq] -> uint2 {h(k0),h(k0+1) | h(k0+8),h(k0+9)}
__device__ uint2 g_Bf[KSTEPS * 64 * 4];

static __device__ __forceinline__ uint32_t s2u(const void* p) {
    uint32_t a;
    asm("{ .reg .u64 t; cvta.to.shared.u64 t, %1; cvt.u32.u64 %0, t; }" : "=r"(a) : "l"(p));
    return a;
}

static __device__ __forceinline__ void ldsm_x4(uint32_t& r0, uint32_t& r1,
                                               uint32_t& r2, uint32_t& r3,
                                               uint32_t addr) {
    asm volatile("ldmatrix.sync.aligned.m8n8.x4.shared.b16 {%0,%1,%2,%3}, [%4];"
                 : "=r"(r0), "=r"(r1), "=r"(r2), "=r"(r3) : "r"(addr));
}

static __device__ __forceinline__ void mma16816(float& d0, float& d1, float& d2, float& d3,
                                                uint32_t a0, uint32_t a1, uint32_t a2, uint32_t a3,
                                                uint32_t b0, uint32_t b1) {
    asm volatile(
        "mma.sync.aligned.m16n8k16.row.col.f32.f16.f16.f32 "
        "{%0,%1,%2,%3}, {%4,%5,%6,%7}, {%8,%9}, {%0,%1,%2,%3};"
        : "+f"(d0), "+f"(d1), "+f"(d2), "+f"(d3)
        : "r"(a0), "r"(a1), "r"(a2), "r"(a3), "r"(b0), "r"(b1));
}

// ---------------------------------------------------------------------------
// Prep: cp fp32 (seen as [k][o], k = i*12+c) -> fragment-ordered fp16 g_Bf.
// ---------------------------------------------------------------------------
__global__ void bspline_prep_kernel(const float* __restrict__ cp) {
    int tid = blockIdx.x * blockDim.x + threadIdx.x;
    if (tid < KSTEPS * 64 * 4) {
        int kq = tid & 3;
        int n = (tid >> 2) & 63;
        int kstep = tid >> 8;
        int k0 = kstep * 16 + kq * 2;
        __half h0 = __float2half_rn(cp[(k0 + 0) * 64 + n]);
        __half h1 = __float2half_rn(cp[(k0 + 1) * 64 + n]);
        __half h2 = __float2half_rn(cp[(k0 + 8) * 64 + n]);
        __half h3 = __float2half_rn(cp[(k0 + 9) * 64 + n]);
        uint2 v;
        v.x = (uint32_t)__half_as_ushort(h0) | ((uint32_t)__half_as_ushort(h1) << 16);
        v.y = (uint32_t)__half_as_ushort(h2) | ((uint32_t)__half_as_ushort(h3) << 16);
        g_Bf[tid] = v;
    }
}

// ---------------------------------------------------------------------------
// Main kernel: one CTA = 64 rows, 8 warps = 4(M) x 2(N), warp tile M16xN32.
// ---------------------------------------------------------------------------
__global__ __launch_bounds__(THREADS, 2)
void bspline_hmma_kernel(const float* __restrict__ x,
                         float* __restrict__ out,
                         int nrows)
{
    extern __shared__ char sm[];
    const uint32_t sb = s2u(sm);
    const int t = threadIdx.x;
    const int wid = t >> 5;
    const int lid = t & 31;
    const int row0 = blockIdx.x * M_TILE;

    float* Tk = (float*)(sm + SMEM_TK);
    if (t < 16) {
        int k = t - 3;
        k = max(0, min(9, k));
        Tk[t] = (float)k / 9.0f;
    }
    __syncthreads();

    // ---------------- Phase 1: build A tile in SMEM (fp16) ----------------
    // 64 rows x 64 i-windows = 4096 pairs, 16 per thread, i fastest.
    #pragma unroll
    for (int s = 0; s < 16; s++) {
        const int p = s * THREADS + t;
        const int r = p >> 6;
        const int i = p & 63;
        const int row = min(row0 + r, nrows - 1);

        float xc = __ldg(x + (size_t)row * DIMS + i);
        xc = fminf(fmaxf(xc, 0.0f), 1.0f);

        int j = 3;
        #pragma unroll
        for (int k = 4; k <= 11; k++) j += (xc >= Tk[k]) ? 1 : 0;

        const float l1 = xc - Tk[j];
        const float r1 = Tk[j + 1] - xc;
        const float l2 = xc - Tk[j - 1];
        const float r2 = Tk[j + 2] - xc;
        const float l3 = xc - Tk[j - 2];
        const float r3 = Tk[j + 3] - xc;

        float N0 = 1.0f, N1, N2, N3, tmp, sv;
        tmp = __fdividef(N0, r1 + l1); N0 = r1 * tmp; N1 = l1 * tmp;
        tmp = __fdividef(N0, r1 + l2); N0 = r1 * tmp; sv = l2 * tmp;
        tmp = __fdividef(N1, r2 + l1); N1 = sv + r2 * tmp; N2 = l1 * tmp;
        tmp = __fdividef(N0, r1 + l3); N0 = r1 * tmp; sv = l3 * tmp;
        tmp = __fdividef(N1, r2 + l2); N1 = sv + r2 * tmp; sv = l2 * tmp;
        tmp = __fdividef(N2, r3 + l1); N2 = sv + r3 * tmp; N3 = l1 * tmp;

        const int c0 = j - 3;   // 0..8

        // Pack 4 weights into a u64 and funnel into the 24B (3 x u64) window.
        uint64_t w64 = (uint64_t)__half_as_ushort(__float2half_rn(N0))
                     | ((uint64_t)__half_as_ushort(__float2half_rn(N1)) << 16)
                     | ((uint64_t)__half_as_ushort(__float2half_rn(N2)) << 32)
                     | ((uint64_t)__half_as_ushort(__float2half_rn(N3)) << 48);
        const int sl = c0 >> 2;            // u64 slot 0..2
        const int rs = (c0 & 3) * 16;      // bit offset within slot
        const uint64_t lo = w64 << rs;
        const uint64_t hi = rs ? (w64 >> (64 - rs)) : 0ULL;

        const uint64_t a0 = (sl == 0) ? lo : 0ULL;
        const uint64_t a1 = (sl == 1) ? lo : ((sl == 0) ? hi : 0ULL);
        const uint64_t a2 = (sl == 2) ? lo : ((sl == 1) ? hi : 0ULL);

        const uint32_t w = sb + (uint32_t)r * A_PITCH_B + (uint32_t)i * 24u;
        asm volatile("st.shared.u64 [%0], %1;" :: "r"(w),      "l"(a0) : "memory");
        asm volatile("st.shared.u64 [%0], %1;" :: "r"(w + 8),  "l"(a1) : "memory");
        asm volatile("st.shared.u64 [%0], %1;" :: "r"(w + 16), "l"(a2) : "memory");
    }
    __syncthreads();

    // ---------------- Phase 2: mma.sync mainloop ----------------
    const int mbase = (wid >> 1) * 16;      // 0,16,32,48
    const int nbase = (wid & 1) * 32;       // 0,32

    // ldmatrix x4 per-lane address: lanes 0-7 rows 0-7 col 0, 8-15 rows 8-15
    // col 0, 16-23 rows 0-7 col 16B, 24-31 rows 8-15 col 16B.
    const int lrow = (lid & 7) + ((lid >> 3) & 1) * 8;
    const int lcol = (lid >> 4) * 16;
    uint32_t aAddr = sb + (uint32_t)(mbase + lrow) * A_PITCH_B + lcol;

    const uint2* __restrict__ Bf = g_Bf;
    const int bLane = (nbase + (lid >> 2)) * 4 + (lid & 3);

    float acc[4][4];
    #pragma unroll
    for (int nt = 0; nt < 4; nt++)
        #pragma unroll
        for (int q = 0; q < 4; q++) acc[nt][q] = 0.0f;

    #pragma unroll 4
    for (int ks = 0; ks < KSTEPS; ks++) {
        uint32_t a[4];
        ldsm_x4(a[0], a[1], a[2], a[3], aAddr + ks * 32);

        uint2 b[4];
        const int bi = ks * 256 + bLane;
        #pragma unroll
        for (int nt = 0; nt < 4; nt++) b[nt] = __ldg(Bf + bi + nt * 32);

        #pragma unroll
        for (int nt = 0; nt < 4; nt++)
            mma16816(acc[nt][0], acc[nt][1], acc[nt][2], acc[nt][3],
                     a[0], a[1], a[2], a[3], b[nt].x, b[nt].y);
    }

    // ---------------- Epilogue: direct float2 stores ----------------
    const int rquad = lid >> 2;              // 0..7
    const int npair = (lid & 3) * 2;         // 0,2,4,6
    #pragma unroll
    for (int nt = 0; nt < 4; nt++) {
        const int col = nbase + nt * 8 + npair;
        const int rA = row0 + mbase + rquad;
        const int rB = rA + 8;
        if (rA < nrows)
            *(float2*)(out + (size_t)rA * DIMS + col) = make_float2(acc[nt][0], acc[nt][1]);
        if (rB < nrows)
            *(float2*)(out + (size_t)rB * DIMS + col) = make_float2(acc[nt][2], acc[nt][3]);
    }
}

extern "C" void kernel_launch(void* const* d_in, const int* in_sizes, int n_in,
                              void* d_out, int out_size)
{
    const float* x  = (const float*)d_in[0];   // (65536, 64)
    const float* cp = (const float*)d_in[1];   // (64, 12, 64) == B[768][64]
    float* out = (float*)d_out;

    const int nrows = in_sizes[0] / DIMS;

    bspline_prep_kernel<<<(KSTEPS * 64 * 4 + 255) / 256, 256>>>(cp);

    cudaFuncSetAttribute(bspline_hmma_kernel,
                         cudaFuncAttributeMaxDynamicSharedMemorySize, SMEM_TOTAL);
    const int grid = (nrows + M_TILE - 1) / M_TILE;
    bspline_hmma_kernel<<<grid, THREADS, SMEM_TOTAL>>>(x, out, nrows);
}

// round 5
// speedup vs baseline: 3.2989x; 1.1207x over previous
#include <cuda_runtime.h>
#include <cuda_fp16.h>
#include <cstdint>

// ============================================================================
// BSpline via warp-level mma.sync (HMMA).
//   out[b,o] = sum_{i,c} basis(x[b,i])[c] * cp[i,c,o]
//   = GEMM: A (rows x 768) * B (768 x 64), k = i*12 + c.
// R5: kill the MUFU.RCP chains — per-span reciprocal table (9 spans x
//   {6 knots, 6 recips}) in SMEM; span via min(8,(int)(x*9)). float4 x loads.
//   Software-pipelined mainloop.
// ============================================================================

#define DIMS 64
#define KSTEPS 48          // 768 / 16
#define M_TILE 64
#define THREADS 256

#define A_PITCH_B 1552     // bytes per A row: 776 halfs; odd multiple of 16B
#define SMEM_A_BYTES (M_TILE * A_PITCH_B)        // 99328
#define SMEM_TAB SMEM_A_BYTES                    // 9 * 12 floats = 432 B
#define SMEM_TOTAL (SMEM_A_BYTES + 512)

// B fragments: [kstep][n][kq] -> uint2 {h(k0),h(k0+1) | h(k0+8),h(k0+9)}
__device__ uint2 g_Bf[KSTEPS * 64 * 4];

static __device__ __forceinline__ uint32_t s2u(const void* p) {
    uint32_t a;
    asm("{ .reg .u64 t; cvta.to.shared.u64 t, %1; cvt.u32.u64 %0, t; }" : "=r"(a) : "l"(p));
    return a;
}

static __device__ __forceinline__ void ldsm_x4(uint32_t& r0, uint32_t& r1,
                                               uint32_t& r2, uint32_t& r3,
                                               uint32_t addr) {
    asm volatile("ldmatrix.sync.aligned.m8n8.x4.shared.b16 {%0,%1,%2,%3}, [%4];"
                 : "=r"(r0), "=r"(r1), "=r"(r2), "=r"(r3) : "r"(addr));
}

static __device__ __forceinline__ void mma16816(float& d0, float& d1, float& d2, float& d3,
                                                uint32_t a0, uint32_t a1, uint32_t a2, uint32_t a3,
                                                uint32_t b0, uint32_t b1) {
    asm("mma.sync.aligned.m16n8k16.row.col.f32.f16.f16.f32 "
        "{%0,%1,%2,%3}, {%4,%5,%6,%7}, {%8,%9}, {%0,%1,%2,%3};"
        : "+f"(d0), "+f"(d1), "+f"(d2), "+f"(d3)
        : "r"(a0), "r"(a1), "r"(a2), "r"(a3), "r"(b0), "r"(b1));
}

// Knot helper: T[k] = clamp(k-3,0,9)/9, matches numpy f32 construction.
static __device__ __forceinline__ float knotv(int k) {
    int v = max(0, min(9, k - 3));
    return (float)v / 9.0f;
}

// ---------------------------------------------------------------------------
// Prep: cp fp32 (seen as [k][o], k = i*12+c) -> fragment-ordered fp16 g_Bf.
// ---------------------------------------------------------------------------
__global__ void bspline_prep_kernel(const float* __restrict__ cp) {
    int tid = blockIdx.x * blockDim.x + threadIdx.x;
    if (tid < KSTEPS * 64 * 4) {
        int kq = tid & 3;
        int n = (tid >> 2) & 63;
        int kstep = tid >> 8;
        int k0 = kstep * 16 + kq * 2;
        __half h0 = __float2half_rn(cp[(k0 + 0) * 64 + n]);
        __half h1 = __float2half_rn(cp[(k0 + 1) * 64 + n]);
        __half h2 = __float2half_rn(cp[(k0 + 8) * 64 + n]);
        __half h3 = __float2half_rn(cp[(k0 + 9) * 64 + n]);
        uint2 v;
        v.x = (uint32_t)__half_as_ushort(h0) | ((uint32_t)__half_as_ushort(h1) << 16);
        v.y = (uint32_t)__half_as_ushort(h2) | ((uint32_t)__half_as_ushort(h3) << 16);
        g_Bf[tid] = v;
    }
}

// ---------------------------------------------------------------------------
// Main kernel: one CTA = 64 rows, 8 warps = 4(M) x 2(N), warp tile M16xN32.
// ---------------------------------------------------------------------------
__global__ __launch_bounds__(THREADS, 2)
void bspline_hmma_kernel(const float* __restrict__ x,
                         float* __restrict__ out,
                         int nrows)
{
    extern __shared__ char sm[];
    const uint32_t sb = s2u(sm);
    const int t = threadIdx.x;
    const int wid = t >> 5;
    const int lid = t & 31;
    const int row0 = blockIdx.x * M_TILE;

    // Per-span table: 12 floats = {T[j-2],T[j-1],T[j],T[j+1], T[j+2],T[j+3],
    //                              i1,i2a, i2b,i3a,i3b,i3c}, j = s+3, s in 0..8
    float* tab = (float*)(sm + SMEM_TAB);
    if (t < 9) {
        const int j = t + 3;
        float* e = tab + t * 12;
        e[0] = knotv(j - 2); e[1] = knotv(j - 1); e[2] = knotv(j);
        e[3] = knotv(j + 1); e[4] = knotv(j + 2); e[5] = knotv(j + 3);
        e[6]  = 1.0f / (e[3] - e[2]);   // i1
        e[7]  = 1.0f / (e[3] - e[1]);   // i2a
        e[8]  = 1.0f / (e[4] - e[2]);   // i2b
        e[9]  = 1.0f / (e[3] - e[0]);   // i3a
        e[10] = 1.0f / (e[4] - e[1]);   // i3b
        e[11] = 1.0f / (e[5] - e[2]);   // i3c
    }
    __syncthreads();

    // ---------------- Phase 1: build A tile in SMEM (fp16) ----------------
    // 64 rows x 16 i-quads = 1024 tasks, 4 per thread; each task: 1 LDG.128
    // of x, 4 windows of de Boor (table recips, no division), 12 STS.64.
    #pragma unroll
    for (int s = 0; s < 4; s++) {
        const int p = s * THREADS + t;
        const int r = p >> 4;                 // row in tile
        const int iq = p & 15;                // i quad
        const int row = min(row0 + r, nrows - 1);

        const float4 xv = __ldg((const float4*)(x + (size_t)row * DIMS + iq * 4));
        const uint32_t wbase = sb + (uint32_t)r * A_PITCH_B + (uint32_t)iq * 96u;

        #pragma unroll
        for (int u = 0; u < 4; u++) {
            float xc = (u == 0) ? xv.x : (u == 1) ? xv.y : (u == 2) ? xv.z : xv.w;
            xc = fminf(fmaxf(xc, 0.0f), 1.0f);

            const int s9 = min(8, (int)(xc * 9.0f));
            const float4* tb = (const float4*)(tab + s9 * 12);
            const float4 t0 = tb[0];
            const float4 t1 = tb[1];
            const float4 t2 = tb[2];

            const float l1 = xc - t0.z, r1 = t0.w - xc;
            const float l2 = xc - t0.y, r2 = t1.x - xc;
            const float l3 = xc - t0.x, r3 = t1.y - xc;

            float N0, N1, N2, N3, tmp, sv;
            tmp = t1.z;                      // N0(=1) * i1
            N0 = r1 * tmp; N1 = l1 * tmp;
            tmp = N0 * t1.w;                 // i2a
            N0 = r1 * tmp; sv = l2 * tmp;
            tmp = N1 * t2.x;                 // i2b
            N1 = fmaf(r2, tmp, sv); N2 = l1 * tmp;
            tmp = N0 * t2.y;                 // i3a
            N0 = r1 * tmp; sv = l3 * tmp;
            tmp = N1 * t2.z;                 // i3b
            N1 = fmaf(r2, tmp, sv); sv = l2 * tmp;
            tmp = N2 * t2.w;                 // i3c
            N2 = fmaf(r3, tmp, sv); N3 = l1 * tmp;

            // Pack 4 halfs -> u64, funnel into 24B (3 x u64) window at slot c0.
            const uint32_t lo2 = __float22half2_rn(make_float2(N0, N1)).x
                ? 0u : 0u;  // (dummy to keep type; real pack below)
            (void)lo2;
            uint32_t p01, p23;
            asm("cvt.rn.f16x2.f32 %0, %2, %1;" : "=r"(p01) : "f"(N0), "f"(N1));
            asm("cvt.rn.f16x2.f32 %0, %2, %1;" : "=r"(p23) : "f"(N2), "f"(N3));
            const uint64_t w64 = (uint64_t)p01 | ((uint64_t)p23 << 32);

            const int c0 = s9;               // j-3
            const int sl = c0 >> 2;
            const int rs = (c0 & 3) * 16;
            const uint64_t lo = w64 << rs;
            const uint64_t hi = rs ? (w64 >> (64 - rs)) : 0ULL;

            const uint64_t a0 = (sl == 0) ? lo : 0ULL;
            const uint64_t a1 = (sl == 1) ? lo : ((sl == 0) ? hi : 0ULL);
            const uint64_t a2 = (sl == 2) ? lo : ((sl == 1) ? hi : 0ULL);

            const uint32_t w = wbase + (uint32_t)u * 24u;
            asm volatile("st.shared.u64 [%0], %1;" :: "r"(w),      "l"(a0) : "memory");
            asm volatile("st.shared.u64 [%0], %1;" :: "r"(w + 8),  "l"(a1) : "memory");
            asm volatile("st.shared.u64 [%0], %1;" :: "r"(w + 16), "l"(a2) : "memory");
        }
    }
    __syncthreads();

    // ---------------- Phase 2: mma.sync mainloop (pipelined) ----------------
    const int mbase = (wid >> 1) * 16;      // 0,16,32,48
    const int nbase = (wid & 1) * 32;       // 0,32

    const int lrow = (lid & 7) + ((lid >> 3) & 1) * 8;
    const int lcol = (lid >> 4) * 16;
    const uint32_t aAddr = sb + (uint32_t)(mbase + lrow) * A_PITCH_B + lcol;

    const uint2* __restrict__ Bf = g_Bf;
    const int bLane = (nbase + (lid >> 2)) * 4 + (lid & 3);

    float acc[4][4];
    #pragma unroll
    for (int nt = 0; nt < 4; nt++)
        #pragma unroll
        for (int q = 0; q < 4; q++) acc[nt][q] = 0.0f;

    uint32_t a[2][4];
    uint2 b[2][4];

    // prologue: stage ks=0
    ldsm_x4(a[0][0], a[0][1], a[0][2], a[0][3], aAddr);
    #pragma unroll
    for (int nt = 0; nt < 4; nt++) b[0][nt] = __ldg(Bf + bLane + nt * 32);

    #pragma unroll 4
    for (int ks = 0; ks < KSTEPS; ks++) {
        const int cur = ks & 1;
        const int nxt = cur ^ 1;
        if (ks + 1 < KSTEPS) {
            ldsm_x4(a[nxt][0], a[nxt][1], a[nxt][2], a[nxt][3],
                    aAddr + (ks + 1) * 32);
            const int bi = (ks + 1) * 256 + bLane;
            #pragma unroll
            for (int nt = 0; nt < 4; nt++) b[nxt][nt] = __ldg(Bf + bi + nt * 32);
        }
        #pragma unroll
        for (int nt = 0; nt < 4; nt++)
            mma16816(acc[nt][0], acc[nt][1], acc[nt][2], acc[nt][3],
                     a[cur][0], a[cur][1], a[cur][2], a[cur][3],
                     b[cur][nt].x, b[cur][nt].y);
    }

    // ---------------- Epilogue: direct float2 stores ----------------
    const int rquad = lid >> 2;
    const int npair = (lid & 3) * 2;
    #pragma unroll
    for (int nt = 0; nt < 4; nt++) {
        const int col = nbase + nt * 8 + npair;
        const int rA = row0 + mbase + rquad;
        const int rB = rA + 8;
        if (rA < nrows)
            *(float2*)(out + (size_t)rA * DIMS + col) = make_float2(acc[nt][0], acc[nt][1]);
        if (rB < nrows)
            *(float2*)(out + (size_t)rB * DIMS + col) = make_float2(acc[nt][2], acc[nt][3]);
    }
}

extern "C" void kernel_launch(void* const* d_in, const int* in_sizes, int n_in,
                              void* d_out, int out_size)
{
    const float* x  = (const float*)d_in[0];   // (65536, 64)
    const float* cp = (const float*)d_in[1];   // (64, 12, 64) == B[768][64]
    float* out = (float*)d_out;

    const int nrows = in_sizes[0] / DIMS;

    bspline_prep_kernel<<<(KSTEPS * 64 * 4 + 255) / 256, 256>>>(cp);

    cudaFuncSetAttribute(bspline_hmma_kernel,
                         cudaFuncAttributeMaxDynamicSharedMemorySize, SMEM_TOTAL);
    const int grid = (nrows + M_TILE - 1) / M_TILE;
    bspline_hmma_kernel<<<grid, THREADS, SMEM_TOTAL>>>(x, out, nrows);
}